// round 3
// baseline (speedup 1.0000x reference)
#include <cuda_runtime.h>
#include <cuda_bf16.h>

#define NT     160
#define FEAT   144
#define YDIM   25
#define EDGE_R 4864
#define NPATH  19

// Per-path tables (enumeration order = reference loops)
__constant__ int c_lo[NPATH]    = {0,0,0,1,1,1,1,1,1,1,2,2,2,2,2,2,2,2,2};
__constant__ int c_li[NPATH]    = {0,1,2,0,1,1,1,2,2,2,0,1,1,1,2,2,2,2,2};
__constant__ int c_lf[NPATH]    = {0,1,2,1,0,1,2,1,2,3,2,1,2,3,0,1,2,3,4};
__constant__ int c_cgoff[NPATH] = {0,1,10,35,44,53,80,125,170,245,350,375,420,495,600,625,700,825,1000};
__constant__ int c_cyoff[NPATH] = {0,1,4,9,12,21,30,39,54,69,84,89,104,119,134,159,184,209,234};
__constant__ int c_pair[NPATH]  = {0,1,2,3,4,4,4,5,5,5,6,7,7,7,8,8,8,8,8};
__constant__ int c_k[NPATH]     = {0,0,0,0,0,1,2,0,1,2,0,0,1,2,0,1,2,3,4};
// Per (lo,li) pair: padded G'' word base, nlf
__constant__ int c_gw[9]   = {0,20,40,60,120,276,432,532,792};
__constant__ int c_nlf9[9] = {1,1,1,1,3,3,1,3,5};
__constant__ int c_finoff[3] = {0,16,64};

__global__ void zero_kernel(float* out, int n) {
    int i = blockIdx.x * blockDim.x + threadIdx.x;
    if (i < n) out[i] = 0.f;
}

// acc += R_row . G_row over 4*NLF float4 (16*NLF words, v*nlf+k interleaved).
// R comes straight from global (coalesced; same-u lanes dedup), G from padded smem.
template<int NLF>
__device__ __forceinline__ float pairdot_g(const float4* __restrict__ gR,
                                           const float4* __restrict__ sG4,
                                           int rbase4, int gf4, int u, int o) {
    const float4* r = gR + rbase4 + u * (4 * NLF);
    const float4* g = sG4 + gf4 + o * (4 * NLF + 1);
    float acc = 0.f;
    #pragma unroll
    for (int j = 0; j < 4 * NLF; ++j) {
        float4 a = __ldg(&r[j]);
        float4 b = g[j];
        acc = fmaf(a.x, b.x, acc);
        acc = fmaf(a.y, b.y, acc);
        acc = fmaf(a.z, b.z, acc);
        acc = fmaf(a.w, b.w, acc);
    }
    return acc;
}

__global__ void __launch_bounds__(NT, 8)
tp_kernel(const float* __restrict__ feat, const float* __restrict__ rbf,
          const float* __restrict__ Y,    const float* __restrict__ cg,
          const float* __restrict__ W,    const int* __restrict__ aidx,
          const int* __restrict__ bidx,   float* __restrict__ out, int E)
{
    __shared__ float4 sG4[303];    // padded/interleaved W*G, 1212 words
    __shared__ float  sF[FEAT];
    __shared__ float  sY[YDIM];
    __shared__ float  sCY[259];

    const int e   = blockIdx.x;
    const int tid = threadIdx.x;
    if (e >= E) return;

    const int a = aidx[e];
    const int b = bidx[e];
    const float4* gR = reinterpret_cast<const float4*>(rbf + (size_t)e * EDGE_R);

    // ---- Phase A: stage F (gather) and Y only ----
    if (tid < 36)
        reinterpret_cast<float4*>(sF)[tid] =
            reinterpret_cast<const float4*>(feat + (size_t)b * FEAT)[tid];
    if (tid >= 64 && tid < 64 + YDIM)
        sY[tid - 64] = Y[(size_t)e * YDIM + (tid - 64)];
    __syncthreads();

    // ---- Phase B1: CY[o,i] = sum_f cg[o,i,f] * Y[lf^2+f] ----
    #pragma unroll
    for (int p = 0; p < NPATH; ++p) {
        const int lo = c_lo[p], li = c_li[p], lf = c_lf[p];
        const int doo = 2 * lo + 1, di = 2 * li + 1, df = 2 * lf + 1;
        if (tid < doo * di) {
            const int cgb = c_cgoff[p] + tid * df;
            const int yb  = lf * lf;
            float s = 0.f;
            for (int f = 0; f < df; ++f)
                s = fmaf(__ldg(&cg[cgb + f]), sY[yb + f], s);
            sCY[c_cyoff[p] + tid] = s;
        }
    }
    __syncthreads();

    // ---- Phase B2: G''[pair][o][v*nlf+k] = W_p * sum_i CY[o,i]*F[v,i] ----
    float* sG = reinterpret_cast<float*>(sG4);
    #pragma unroll
    for (int p = 0; p < NPATH; ++p) {
        const int lo = c_lo[p], li = c_li[p];
        const int doo = 2 * lo + 1, di = 2 * li + 1;
        const int n = 16 * doo;
        if (tid < n) {
            const int v = tid / doo, o = tid - v * doo;
            const float* cy = &sCY[c_cyoff[p] + o * di];
            const float* fv = &sF[c_finoff[li] + v * di];
            float s = 0.f;
            for (int i2 = 0; i2 < di; ++i2) s = fmaf(cy[i2], fv[i2], s);
            const int pr  = c_pair[p];
            const int nlf = c_nlf9[pr];
            sG[c_gw[pr] + o * (16 * nlf + 4) + v * nlf + c_k[p]] = __ldg(&W[p]) * s;
        }
    }
    __syncthreads();

    // ---- Phase C: one thread per output element; R streamed from global ----
    // R pair bases in float4: (0,0)=0 (0,1)=64 (0,2)=128 (1,0)=192 (1,1)=256
    // (1,2)=448 (2,0)=640 (2,1)=704 (2,2)=896
    if (tid < FEAT) {
        float acc;
        int outi;
        if (tid < 16) {                       // lo=0: u=tid, o=0
            const int u = tid;
            acc  = pairdot_g<1>(gR, sG4,   0,   0, u, 0);
            acc += pairdot_g<1>(gR, sG4,  64,   5, u, 0);
            acc += pairdot_g<1>(gR, sG4, 128,  10, u, 0);
            outi = u;
        } else if (tid < 64) {                // lo=1
            const int s = tid - 16, u = s / 3, o = s - u * 3;
            acc  = pairdot_g<1>(gR, sG4, 192,  15, u, o);
            acc += pairdot_g<3>(gR, sG4, 256,  30, u, o);
            acc += pairdot_g<3>(gR, sG4, 448,  69, u, o);
            outi = 16 + u * 3 + o;
        } else {                              // lo=2
            const int s = tid - 64, u = s / 5, o = s - u * 5;
            acc  = pairdot_g<1>(gR, sG4, 640, 108, u, o);
            acc += pairdot_g<3>(gR, sG4, 704, 133, u, o);
            acc += pairdot_g<5>(gR, sG4, 896, 198, u, o);
            outi = 64 + u * 5 + o;
        }
        atomicAdd(out + (size_t)a * FEAT + outi, acc);
    }
}

extern "C" void kernel_launch(void* const* d_in, const int* in_sizes, int n_in,
                              void* d_out, int out_size)
{
    const float* feat = (const float*)d_in[0];
    const float* rbf  = (const float*)d_in[1];
    const float* Y    = (const float*)d_in[2];
    const float* cg   = (const float*)d_in[3];
    const float* W    = (const float*)d_in[4];
    const int*   a    = (const int*)d_in[5];
    const int*   b    = (const int*)d_in[6];
    float* out = (float*)d_out;

    const int E = in_sizes[1] / EDGE_R;

    zero_kernel<<<(out_size + 255) / 256, 256>>>(out, out_size);
    tp_kernel<<<E, NT>>>(feat, rbf, Y, cg, W, a, b, out, E);
}

// round 4
// speedup vs baseline: 1.7663x; 1.7663x over previous
#include <cuda_runtime.h>
#include <cuda_bf16.h>

#define FEAT    144
#define YDIM    25
#define EDGE_R  4864
#define NPATH   19
#define MAXE    50000
#define GF4     304          // padded G'' per edge in float4 (1216 words)

// Per-path tables (enumeration order = reference loops)
__constant__ int c_lo[NPATH]    = {0,0,0,1,1,1,1,1,1,1,2,2,2,2,2,2,2,2,2};
__constant__ int c_li[NPATH]    = {0,1,2,0,1,1,1,2,2,2,0,1,1,1,2,2,2,2,2};
__constant__ int c_lf[NPATH]    = {0,1,2,1,0,1,2,1,2,3,2,1,2,3,0,1,2,3,4};
__constant__ int c_cgoff[NPATH] = {0,1,10,35,44,53,80,125,170,245,350,375,420,495,600,625,700,825,1000};
__constant__ int c_cyoff[NPATH] = {0,1,4,9,12,21,30,39,54,69,84,89,104,119,134,159,184,209,234};
__constant__ int c_b2off[NPATH] = {0,16,32,48,96,144,192,240,288,336,384,464,544,624,704,784,864,944,1024};
__constant__ int c_pair[NPATH]  = {0,1,2,3,4,4,4,5,5,5,6,7,7,7,8,8,8,8,8};
__constant__ int c_k[NPATH]     = {0,0,0,0,0,1,2,0,1,2,0,0,1,2,0,1,2,3,4};
__constant__ int c_gw[9]        = {0,20,40,60,120,276,432,532,792};   // padded word base per (lo,li) pair
__constant__ int c_nlf9[9]      = {1,1,1,1,3,3,1,3,5};
__constant__ int c_finoff[3]    = {0,16,64};

// Scratch + descriptor tables (static device memory — no allocation)
__device__ float4 g_scratch[(size_t)MAXE * GF4];   // per-edge padded W*G''
__device__ int4   g_b1[259];                       // {wcg_base, df, y_base, cy_dst}
__device__ int4   g_b2[1104];                      // {cy_base, f_base, di, g_dst}
__device__ float  g_wcg[1225];                     // cg * W[path]

__global__ void zero_kernel(float* out, int n) {
    int i = blockIdx.x * blockDim.x + threadIdx.x;
    if (i < n) out[i] = 0.f;
}

// Build flat descriptor tables + W-folded cg. Deterministic, rerun every launch.
__global__ void build_tables(const float* __restrict__ cg, const float* __restrict__ W) {
    int t = blockIdx.x * blockDim.x + threadIdx.x;
    if (t < 259) {                       // B1 entries
        int p = 0;
        for (int q = 1; q < NPATH; ++q) if (t >= c_cyoff[q]) p = q;
        int j  = t - c_cyoff[p];
        int lf = c_lf[p], df = 2 * lf + 1;
        g_b1[t] = make_int4(c_cgoff[p] + j * df, df, lf * lf, t);
    }
    if (t < 1104) {                      // B2 entries
        int p = 0;
        for (int q = 1; q < NPATH; ++q) if (t >= c_b2off[q]) p = q;
        int j  = t - c_b2off[p];
        int lo = c_lo[p], li = c_li[p];
        int doo = 2 * lo + 1, di = 2 * li + 1;
        int v = j / doo, o = j - v * doo;
        int pr = c_pair[p], nlf = c_nlf9[pr];
        int gdst = c_gw[pr] + o * (16 * nlf + 4) + v * nlf + c_k[p];
        g_b2[t] = make_int4(c_cyoff[p] + o * di, c_finoff[li] + v * di, di, gdst);
    }
    if (t < 1225) {                      // W-folded cg
        int p = 0;
        for (int q = 1; q < NPATH; ++q) if (t >= c_cgoff[q]) p = q;
        g_wcg[t] = cg[t] * W[p];
    }
}

// ---- K1: per-edge G'' = (W*cg*Y) contracted with gathered F; write to scratch ----
__global__ void __launch_bounds__(128)
k1_kernel(const float* __restrict__ feat, const float* __restrict__ Y,
          const int* __restrict__ bidx, int E)
{
    __shared__ float  sF[FEAT];
    __shared__ float  sY[YDIM];
    __shared__ float  sCY[259];
    __shared__ float4 sG[GF4];

    const int e = blockIdx.x, tid = threadIdx.x;
    const int b = bidx[e];

    if (tid < 36)
        reinterpret_cast<float4*>(sF)[tid] =
            reinterpret_cast<const float4*>(feat + (size_t)b * FEAT)[tid];
    if (tid >= 64 && tid < 64 + YDIM)
        sY[tid - 64] = Y[(size_t)e * YDIM + (tid - 64)];
    __syncthreads();

    // B1 flat: CY[t] = sum_f wcg[base+f] * Y[yb+f]
    for (int t = tid; t < 259; t += 128) {
        int4 d = __ldg(&g_b1[t]);
        float s = 0.f;
        for (int f = 0; f < d.y; ++f)
            s = fmaf(__ldg(&g_wcg[d.x + f]), sY[d.z + f], s);
        sCY[d.w] = s;
    }
    __syncthreads();

    // B2 flat: G''[gdst] = sum_i CY[cyb+i] * F[fb+i]
    float* sGw = reinterpret_cast<float*>(sG);
    for (int t = tid; t < 1104; t += 128) {
        int4 d = __ldg(&g_b2[t]);
        float s = 0.f;
        for (int i = 0; i < d.z; ++i)
            s = fmaf(sCY[d.x + i], sF[d.y + i], s);
        sGw[d.w] = s;
    }
    __syncthreads();

    float4* dst = g_scratch + (size_t)e * GF4;
    for (int t = tid; t < GF4; t += 128) dst[t] = sG[t];
}

// acc += R_row . G_row over 4*NLF float4; R global (coalesced/dedup), G padded smem.
template<int NLF>
__device__ __forceinline__ float pairdot_g(const float4* __restrict__ gR,
                                           const float4* __restrict__ sG4,
                                           int rbase4, int gf4, int u, int o) {
    const float4* r = gR + rbase4 + u * (4 * NLF);
    const float4* g = sG4 + gf4 + o * (4 * NLF + 1);
    float a0 = 0.f, a1 = 0.f, a2 = 0.f, a3 = 0.f;
    #pragma unroll
    for (int j = 0; j < 4 * NLF; ++j) {
        float4 A = __ldg(&r[j]);
        float4 B = g[j];
        a0 = fmaf(A.x, B.x, a0);
        a1 = fmaf(A.y, B.y, a1);
        a2 = fmaf(A.z, B.z, a2);
        a3 = fmaf(A.w, B.w, a3);
    }
    return (a0 + a1) + (a2 + a3);
}

// ---- K2: streaming contraction out[a] += R . G'' ----
__global__ void __launch_bounds__(160, 8)
k2_kernel(const float* __restrict__ rbf, const int* __restrict__ aidx,
          float* __restrict__ out, int E)
{
    __shared__ float4 sG4[GF4];

    const int e = blockIdx.x, tid = threadIdx.x;
    const int a = aidx[e];
    const float4* gR  = reinterpret_cast<const float4*>(rbf + (size_t)e * EDGE_R);
    const float4* src = g_scratch + (size_t)e * GF4;

    for (int t = tid; t < GF4; t += 160) sG4[t] = __ldg(&src[t]);
    __syncthreads();

    if (tid < FEAT) {
        float acc;
        int outi;
        if (tid < 16) {                       // lo=0
            const int u = tid;
            acc  = pairdot_g<1>(gR, sG4,   0,   0, u, 0);
            acc += pairdot_g<1>(gR, sG4,  64,   5, u, 0);
            acc += pairdot_g<1>(gR, sG4, 128,  10, u, 0);
            outi = u;
        } else if (tid < 64) {                // lo=1
            const int s = tid - 16, u = s / 3, o = s - u * 3;
            acc  = pairdot_g<1>(gR, sG4, 192,  15, u, o);
            acc += pairdot_g<3>(gR, sG4, 256,  30, u, o);
            acc += pairdot_g<3>(gR, sG4, 448,  69, u, o);
            outi = 16 + u * 3 + o;
        } else {                              // lo=2
            const int s = tid - 64, u = s / 5, o = s - u * 5;
            acc  = pairdot_g<1>(gR, sG4, 640, 108, u, o);
            acc += pairdot_g<3>(gR, sG4, 704, 133, u, o);
            acc += pairdot_g<5>(gR, sG4, 896, 198, u, o);
            outi = 64 + u * 5 + o;
        }
        atomicAdd(out + (size_t)a * FEAT + outi, acc);
    }
}

extern "C" void kernel_launch(void* const* d_in, const int* in_sizes, int n_in,
                              void* d_out, int out_size)
{
    const float* feat = (const float*)d_in[0];
    const float* rbf  = (const float*)d_in[1];
    const float* Y    = (const float*)d_in[2];
    const float* cg   = (const float*)d_in[3];
    const float* W    = (const float*)d_in[4];
    const int*   a    = (const int*)d_in[5];
    const int*   b    = (const int*)d_in[6];
    float* out = (float*)d_out;

    const int E = in_sizes[1] / EDGE_R;

    zero_kernel<<<(out_size + 255) / 256, 256>>>(out, out_size);
    build_tables<<<6, 256>>>(cg, W);
    k1_kernel<<<E, 128>>>(feat, Y, b, E);
    k2_kernel<<<E, 160>>>(rbf, a, out, E);
}

// round 5
// speedup vs baseline: 1.9126x; 1.0828x over previous
#include <cuda_runtime.h>
#include <cuda_bf16.h>

#define NT      160
#define FEAT    144
#define YDIM    25
#define EDGE_R  4864
#define NPATH   19

// Per-path tables (enumeration order = reference loops)
__constant__ int c_lo[NPATH]    = {0,0,0,1,1,1,1,1,1,1,2,2,2,2,2,2,2,2,2};
__constant__ int c_li[NPATH]    = {0,1,2,0,1,1,1,2,2,2,0,1,1,1,2,2,2,2,2};
__constant__ int c_lf[NPATH]    = {0,1,2,1,0,1,2,1,2,3,2,1,2,3,0,1,2,3,4};
__constant__ int c_cgoff[NPATH] = {0,1,10,35,44,53,80,125,170,245,350,375,420,495,600,625,700,825,1000};
__constant__ int c_cyoff[NPATH] = {0,1,4,9,12,21,30,39,54,69,84,89,104,119,134,159,184,209,234};
__constant__ int c_b2off[NPATH] = {0,16,32,48,96,144,192,240,288,336,384,464,544,624,704,784,864,944,1024};
__constant__ int c_pair[NPATH]  = {0,1,2,3,4,4,4,5,5,5,6,7,7,7,8,8,8,8,8};
__constant__ int c_k[NPATH]     = {0,0,0,0,0,1,2,0,1,2,0,0,1,2,0,1,2,3,4};
__constant__ int c_gw[9]        = {0,20,40,60,120,276,432,532,792};
__constant__ int c_nlf9[9]      = {1,1,1,1,3,3,1,3,5};
__constant__ int c_finoff[3]    = {0,16,64};

// Precomputed tables (static device memory)
__device__ unsigned int   g_b1p[259];    // wcgb<<9 | yb<<4 | df
__device__ unsigned int   g_b2p[1104];   // gdst<<21 | cyb<<12 | fb<<4 | di
__device__ float          g_wcg[1225];   // cg * W[path]
__device__ unsigned short g_rmap[1216];  // src f4 -> padded smem f4

__global__ void zero_kernel(float* out, int n) {
    int i = blockIdx.x * blockDim.x + threadIdx.x;
    if (i < n) out[i] = 0.f;
}

// Padded R layout per (lo,li) pair: 16 u-rows of (4*nlf+1) float4 each.
// Word stride 16nlf+4 == 20 (mod 32) -> conflict-free across u.
__device__ int map_r(int G4) {
    if (G4 < 256) { int r = G4 >> 6, l = G4 & 63; return r * 80 + (l >> 2) * 5 + (l & 3); }
    else if (G4 < 448) { int l = G4 - 256, u = l / 12; return 320 + u * 13 + (l - u * 12); }
    else if (G4 < 640) { int l = G4 - 448, u = l / 12; return 528 + u * 13 + (l - u * 12); }
    else if (G4 < 704) { int l = G4 - 640; return 736 + (l >> 2) * 5 + (l & 3); }
    else if (G4 < 896) { int l = G4 - 704, u = l / 12; return 816 + u * 13 + (l - u * 12); }
    else { int l = G4 - 896, u = l / 20; return 1024 + u * 21 + (l - u * 20); }
}

__global__ void build_tables(const float* __restrict__ cg, const float* __restrict__ W) {
    int t = blockIdx.x * blockDim.x + threadIdx.x;
    if (t < 259) {
        int p = 0;
        for (int q = 1; q < NPATH; ++q) if (t >= c_cyoff[q]) p = q;
        int j = t - c_cyoff[p], lf = c_lf[p], df = 2 * lf + 1;
        g_b1p[t] = ((unsigned)(c_cgoff[p] + j * df) << 9) | ((unsigned)(lf * lf) << 4) | (unsigned)df;
    }
    if (t < 1104) {
        int p = 0;
        for (int q = 1; q < NPATH; ++q) if (t >= c_b2off[q]) p = q;
        int j = t - c_b2off[p];
        int lo = c_lo[p], li = c_li[p];
        int doo = 2 * lo + 1, di = 2 * li + 1;
        int v = j / doo, o = j - v * doo;
        int pr = c_pair[p], nlf = c_nlf9[pr];
        int gdst = c_gw[pr] + o * (16 * nlf + 4) + v * nlf + c_k[p];
        g_b2p[t] = ((unsigned)gdst << 21) | ((unsigned)(c_cyoff[p] + o * di) << 12)
                 | ((unsigned)(c_finoff[li] + v * di) << 4) | (unsigned)di;
    }
    if (t < 1225) {
        int p = 0;
        for (int q = 1; q < NPATH; ++q) if (t >= c_cgoff[q]) p = q;
        g_wcg[t] = cg[t] * W[p];
    }
    if (t < 1216) g_rmap[t] = (unsigned short)map_r(t);
}

// acc += R_row . G_row over 4*NLF float4 from padded smem (conflict-free, broadcast-dedup)
template<int NLF>
__device__ __forceinline__ float pairdot_s(const float4* __restrict__ sR4,
                                           const float4* __restrict__ sG4,
                                           int rf4, int gf4, int u, int o) {
    const float4* r = sR4 + rf4 + u * (4 * NLF + 1);
    const float4* g = sG4 + gf4 + o * (4 * NLF + 1);
    float a0 = 0.f, a1 = 0.f, a2 = 0.f, a3 = 0.f;
    #pragma unroll
    for (int j = 0; j < 4 * NLF; ++j) {
        float4 A = r[j];
        float4 B = g[j];
        a0 = fmaf(A.x, B.x, a0);
        a1 = fmaf(A.y, B.y, a1);
        a2 = fmaf(A.z, B.z, a2);
        a3 = fmaf(A.w, B.w, a3);
    }
    return (a0 + a1) + (a2 + a3);
}

__global__ void __launch_bounds__(NT, 8)
tp_kernel(const float* __restrict__ feat, const float* __restrict__ rbf,
          const float* __restrict__ Y,    const int* __restrict__ aidx,
          const int* __restrict__ bidx,   float* __restrict__ out, int E)
{
    __shared__ float4 sR4[1360];   // padded R (21.8 KB)
    __shared__ float4 sG4[304];    // padded/interleaved W*G'' (4.9 KB)
    __shared__ float  sF[FEAT];
    __shared__ float  sY[YDIM];
    __shared__ float  sCY[259];

    const int e = blockIdx.x, tid = threadIdx.x;
    const int a = aidx[e];
    const int b = bidx[e];

    // ---- Phase A: coalesced R stage through rmap; F gather; Y ----
    {
        const float4* r4 = reinterpret_cast<const float4*>(rbf + (size_t)e * EDGE_R);
        #pragma unroll
        for (int i = 0; i < 8; ++i) {
            int t = tid + i * NT;
            if (t < 1216) sR4[__ldg(&g_rmap[t])] = __ldg(&r4[t]);
        }
        if (tid < 36)
            reinterpret_cast<float4*>(sF)[tid] =
                reinterpret_cast<const float4*>(feat + (size_t)b * FEAT)[tid];
        if (tid >= 64 && tid < 64 + YDIM)
            sY[tid - 64] = Y[(size_t)e * YDIM + (tid - 64)];
    }
    __syncthreads();

    // ---- Phase B1: CY[t] = sum_f wcg[wcgb+f] * Y[yb+f] ----
    for (int t = tid; t < 259; t += NT) {
        unsigned d = __ldg(&g_b1p[t]);
        int df = d & 15, yb = (d >> 4) & 31, wb = d >> 9;
        float s = 0.f;
        for (int f = 0; f < df; ++f)
            s = fmaf(__ldg(&g_wcg[wb + f]), sY[yb + f], s);
        sCY[t] = s;
    }
    __syncthreads();

    // ---- Phase B2: G''[gdst] = sum_i CY[cyb+i] * F[fb+i] ----
    float* sG = reinterpret_cast<float*>(sG4);
    for (int t = tid; t < 1104; t += NT) {
        unsigned d = __ldg(&g_b2p[t]);
        int di = d & 15, fb = (d >> 4) & 255, cyb = (d >> 12) & 511, gdst = d >> 21;
        float s = 0.f;
        for (int i = 0; i < di; ++i)
            s = fmaf(sCY[cyb + i], sF[fb + i], s);
        sG[gdst] = s;
    }
    __syncthreads();

    // ---- Phase C: one thread per output element, all-smem dot products ----
    if (tid < FEAT) {
        float acc;
        int outi;
        if (tid < 16) {                       // lo=0
            const int u = tid;
            acc  = pairdot_s<1>(sR4, sG4,    0,   0, u, 0);
            acc += pairdot_s<1>(sR4, sG4,   80,   5, u, 0);
            acc += pairdot_s<1>(sR4, sG4,  160,  10, u, 0);
            outi = u;
        } else if (tid < 64) {                // lo=1
            const int s = tid - 16, u = s / 3, o = s - u * 3;
            acc  = pairdot_s<1>(sR4, sG4,  240,  15, u, o);
            acc += pairdot_s<3>(sR4, sG4,  320,  30, u, o);
            acc += pairdot_s<3>(sR4, sG4,  528,  69, u, o);
            outi = 16 + u * 3 + o;
        } else {                              // lo=2
            const int s = tid - 64, u = s / 5, o = s - u * 5;
            acc  = pairdot_s<1>(sR4, sG4,  736, 108, u, o);
            acc += pairdot_s<3>(sR4, sG4,  816, 133, u, o);
            acc += pairdot_s<5>(sR4, sG4, 1024, 198, u, o);
            outi = 64 + u * 5 + o;
        }
        atomicAdd(out + (size_t)a * FEAT + outi, acc);
    }
}

extern "C" void kernel_launch(void* const* d_in, const int* in_sizes, int n_in,
                              void* d_out, int out_size)
{
    const float* feat = (const float*)d_in[0];
    const float* rbf  = (const float*)d_in[1];
    const float* Y    = (const float*)d_in[2];
    const float* cg   = (const float*)d_in[3];
    const float* W    = (const float*)d_in[4];
    const int*   a    = (const int*)d_in[5];
    const int*   b    = (const int*)d_in[6];
    float* out = (float*)d_out;

    const int E = in_sizes[1] / EDGE_R;

    zero_kernel<<<(out_size + 255) / 256, 256>>>(out, out_size);
    build_tables<<<5, 256>>>(cg, W);
    tp_kernel<<<E, NT>>>(feat, rbf, Y, a, b, out, E);
}

// round 6
// speedup vs baseline: 2.1735x; 1.1364x over previous
#include <cuda_runtime.h>
#include <cuda_bf16.h>

#define NT      288
#define FEAT    144
#define YDIM    25
#define EDGE_R  4864
#define NPATH   19

// Per-path tables (enumeration order = reference loops)
__constant__ int c_lo[NPATH]    = {0,0,0,1,1,1,1,1,1,1,2,2,2,2,2,2,2,2,2};
__constant__ int c_li[NPATH]    = {0,1,2,0,1,1,1,2,2,2,0,1,1,1,2,2,2,2,2};
__constant__ int c_lf[NPATH]    = {0,1,2,1,0,1,2,1,2,3,2,1,2,3,0,1,2,3,4};
__constant__ int c_cgoff[NPATH] = {0,1,10,35,44,53,80,125,170,245,350,375,420,495,600,625,700,825,1000};
__constant__ int c_cyoff[NPATH] = {0,1,4,9,12,21,30,39,54,69,84,89,104,119,134,159,184,209,234};
__constant__ int c_b2off[NPATH] = {0,16,32,48,96,144,192,240,288,336,384,464,544,624,704,784,864,944,1024};
__constant__ int c_pair[NPATH]  = {0,1,2,3,4,4,4,5,5,5,6,7,7,7,8,8,8,8,8};
__constant__ int c_k[NPATH]     = {0,0,0,0,0,1,2,0,1,2,0,0,1,2,0,1,2,3,4};
__constant__ int c_gw[9]        = {0,20,40,60,120,276,432,532,792};
__constant__ int c_nlf9[9]      = {1,1,1,1,3,3,1,3,5};
__constant__ int c_finoff[3]    = {0,16,64};

// Precomputed tables (static device memory)
__device__ unsigned int   g_b1p[259];    // wcgb<<9 | yb<<4 | df
__device__ unsigned int   g_b2p[1104];   // gdst<<21 | cyb<<12 | fb<<4 | di
__device__ float          g_wcg[1225];   // cg * W[path]
__device__ unsigned short g_rmap[1216];  // src f4 -> padded smem f4

__global__ void zero_kernel(float* out, int n) {
    int i = blockIdx.x * blockDim.x + threadIdx.x;
    if (i < n) out[i] = 0.f;
}

// Padded R layout per (lo,li) pair: 16 u-rows of (4*nlf+1) float4 each.
// Word stride 16nlf+4 == 20 (mod 32) -> conflict-free across u rows.
__device__ int map_r(int G4) {
    if (G4 < 256) { int r = G4 >> 6, l = G4 & 63; return r * 80 + (l >> 2) * 5 + (l & 3); }
    else if (G4 < 448) { int l = G4 - 256, u = l / 12; return 320 + u * 13 + (l - u * 12); }
    else if (G4 < 640) { int l = G4 - 448, u = l / 12; return 528 + u * 13 + (l - u * 12); }
    else if (G4 < 704) { int l = G4 - 640; return 736 + (l >> 2) * 5 + (l & 3); }
    else if (G4 < 896) { int l = G4 - 704, u = l / 12; return 816 + u * 13 + (l - u * 12); }
    else { int l = G4 - 896, u = l / 20; return 1024 + u * 21 + (l - u * 20); }
}

__global__ void build_tables(const float* __restrict__ cg, const float* __restrict__ W) {
    int t = blockIdx.x * blockDim.x + threadIdx.x;
    if (t < 259) {
        int p = 0;
        for (int q = 1; q < NPATH; ++q) if (t >= c_cyoff[q]) p = q;
        int j = t - c_cyoff[p], lf = c_lf[p], df = 2 * lf + 1;
        g_b1p[t] = ((unsigned)(c_cgoff[p] + j * df) << 9) | ((unsigned)(lf * lf) << 4) | (unsigned)df;
    }
    if (t < 1104) {
        int p = 0;
        for (int q = 1; q < NPATH; ++q) if (t >= c_b2off[q]) p = q;
        int j = t - c_b2off[p];
        int lo = c_lo[p], li = c_li[p];
        int doo = 2 * lo + 1, di = 2 * li + 1;
        int v = j / doo, o = j - v * doo;
        int pr = c_pair[p], nlf = c_nlf9[pr];
        int gdst = c_gw[pr] + o * (16 * nlf + 4) + v * nlf + c_k[p];
        g_b2p[t] = ((unsigned)gdst << 21) | ((unsigned)(c_cyoff[p] + o * di) << 12)
                 | ((unsigned)(c_finoff[li] + v * di) << 4) | (unsigned)di;
    }
    if (t < 1225) {
        int p = 0;
        for (int q = 1; q < NPATH; ++q) if (t >= c_cgoff[q]) p = q;
        g_wcg[t] = cg[t] * W[p];
    }
    if (t < 1216) g_rmap[t] = (unsigned short)map_r(t);
}

// acc += R_row . G_row over 4*NLF float4 from padded smem (conflict-free, broadcast-dedup)
template<int NLF>
__device__ __forceinline__ float pairdot_s(const float4* __restrict__ sR4,
                                           const float4* __restrict__ sG4,
                                           int rf4, int gf4, int u, int o) {
    const float4* r = sR4 + rf4 + u * (4 * NLF + 1);
    const float4* g = sG4 + gf4 + o * (4 * NLF + 1);
    float a0 = 0.f, a1 = 0.f, a2 = 0.f, a3 = 0.f;
    #pragma unroll
    for (int j = 0; j < 4 * NLF; ++j) {
        float4 A = r[j];
        float4 B = g[j];
        a0 = fmaf(A.x, B.x, a0);
        a1 = fmaf(A.y, B.y, a1);
        a2 = fmaf(A.z, B.z, a2);
        a3 = fmaf(A.w, B.w, a3);
    }
    return (a0 + a1) + (a2 + a3);
}

__global__ void __launch_bounds__(NT, 6)
tp_kernel(const float* __restrict__ feat, const float* __restrict__ rbf,
          const float* __restrict__ Y,    const int* __restrict__ aidx,
          const int* __restrict__ bidx,   float* __restrict__ out, int E)
{
    __shared__ float4 sR4[1360];   // padded R (21.8 KB)
    __shared__ float4 sG4[304];    // padded/interleaved W*G'' (4.9 KB)
    __shared__ float  sF[FEAT];
    __shared__ float  sY[YDIM];
    __shared__ float  sCY[259];

    const int e = blockIdx.x, tid = threadIdx.x;
    const int a = aidx[e];
    const int b = bidx[e];

    // ---- Phase A: coalesced R stage through rmap; F gather; Y ----
    {
        const float4* r4 = reinterpret_cast<const float4*>(rbf + (size_t)e * EDGE_R);
        #pragma unroll
        for (int i = 0; i < 5; ++i) {
            int t = tid + i * NT;
            if (t < 1216) sR4[__ldg(&g_rmap[t])] = __ldg(&r4[t]);
        }
        if (tid < 36)
            reinterpret_cast<float4*>(sF)[tid] =
                reinterpret_cast<const float4*>(feat + (size_t)b * FEAT)[tid];
        if (tid >= 64 && tid < 64 + YDIM)
            sY[tid - 64] = Y[(size_t)e * YDIM + (tid - 64)];
    }
    __syncthreads();

    // ---- Phase B1: CY[t] = sum_f wcg[wcgb+f] * Y[yb+f] ----
    if (tid < 259) {
        unsigned d = __ldg(&g_b1p[tid]);
        int df = d & 15, yb = (d >> 4) & 31, wb = d >> 9;
        float s = 0.f;
        for (int f = 0; f < df; ++f)
            s = fmaf(__ldg(&g_wcg[wb + f]), sY[yb + f], s);
        sCY[tid] = s;
    }
    __syncthreads();

    // ---- Phase B2: G''[gdst] = sum_i CY[cyb+i] * F[fb+i] ----
    float* sG = reinterpret_cast<float*>(sG4);
    for (int t = tid; t < 1104; t += NT) {
        unsigned d = __ldg(&g_b2p[t]);
        int di = d & 15, fb = (d >> 4) & 255, cyb = (d >> 12) & 511, gdst = d >> 21;
        float s = 0.f;
        for (int i = 0; i < di; ++i)
            s = fmaf(sCY[cyb + i], sF[fb + i], s);
        sG[gdst] = s;
    }
    __syncthreads();

    // ---- Phase C: balanced split — two threads per lo=1/lo=2 output ----
    // h0 = first two li-pairs, h1 = last li-pair; both REDG-add to global.
    if (tid < 272) {
        float acc;
        int outi;
        if (tid < 16) {                          // lo=0 (full, 48 FMA)
            const int u = tid;
            acc  = pairdot_s<1>(sR4, sG4,    0,   0, u, 0);
            acc += pairdot_s<1>(sR4, sG4,   80,   5, u, 0);
            acc += pairdot_s<1>(sR4, sG4,  160,  10, u, 0);
            outi = u;
        } else if (tid < 64) {                   // lo=1 h0 (64 FMA)
            const int s = tid - 16, u = s / 3, o = s - u * 3;
            acc  = pairdot_s<1>(sR4, sG4,  240,  15, u, o);
            acc += pairdot_s<3>(sR4, sG4,  320,  30, u, o);
            outi = 16 + u * 3 + o;
        } else if (tid < 112) {                  // lo=1 h1 (48 FMA)
            const int s = tid - 64, u = s / 3, o = s - u * 3;
            acc  = pairdot_s<3>(sR4, sG4,  528,  69, u, o);
            outi = 16 + u * 3 + o;
        } else if (tid < 192) {                  // lo=2 h0 (64 FMA)
            const int s = tid - 112, u = s / 5, o = s - u * 5;
            acc  = pairdot_s<1>(sR4, sG4,  736, 108, u, o);
            acc += pairdot_s<3>(sR4, sG4,  816, 133, u, o);
            outi = 64 + u * 5 + o;
        } else {                                 // lo=2 h1 (80 FMA)
            const int s = tid - 192, u = s / 5, o = s - u * 5;
            acc  = pairdot_s<5>(sR4, sG4, 1024, 198, u, o);
            outi = 64 + u * 5 + o;
        }
        atomicAdd(out + (size_t)a * FEAT + outi, acc);
    }
}

extern "C" void kernel_launch(void* const* d_in, const int* in_sizes, int n_in,
                              void* d_out, int out_size)
{
    const float* feat = (const float*)d_in[0];
    const float* rbf  = (const float*)d_in[1];
    const float* Y    = (const float*)d_in[2];
    const float* cg   = (const float*)d_in[3];
    const float* W    = (const float*)d_in[4];
    const int*   a    = (const int*)d_in[5];
    const int*   b    = (const int*)d_in[6];
    float* out = (float*)d_out;

    const int E = in_sizes[1] / EDGE_R;

    zero_kernel<<<(out_size + 255) / 256, 256>>>(out, out_size);
    build_tables<<<5, 256>>>(cg, W);
    tp_kernel<<<E, NT>>>(feat, rbf, Y, a, b, out, E);
}

// round 7
// speedup vs baseline: 2.4603x; 1.1319x over previous
#include <cuda_runtime.h>
#include <cuda_bf16.h>

#define NT      288
#define FEAT    144
#define YDIM    25
#define EDGE_R  4864
#define NPATH   19

// Per-path tables (enumeration order = reference loops)
__constant__ int c_lo[NPATH]    = {0,0,0,1,1,1,1,1,1,1,2,2,2,2,2,2,2,2,2};
__constant__ int c_li[NPATH]    = {0,1,2,0,1,1,1,2,2,2,0,1,1,1,2,2,2,2,2};
__constant__ int c_lf[NPATH]    = {0,1,2,1,0,1,2,1,2,3,2,1,2,3,0,1,2,3,4};
__constant__ int c_cgoff[NPATH] = {0,1,10,35,44,53,80,125,170,245,350,375,420,495,600,625,700,825,1000};
__constant__ int c_cyoff[NPATH] = {0,1,4,9,12,21,30,39,54,69,84,89,104,119,134,159,184,209,234};
__constant__ int c_b2off[NPATH] = {0,16,32,48,96,144,192,240,288,336,384,464,544,624,704,784,864,944,1024};
__constant__ int c_pair[NPATH]  = {0,1,2,3,4,4,4,5,5,5,6,7,7,7,8,8,8,8,8};
__constant__ int c_k[NPATH]     = {0,0,0,0,0,1,2,0,1,2,0,0,1,2,0,1,2,3,4};
__constant__ int c_gw[9]        = {0,20,40,60,120,276,432,532,792};
__constant__ int c_nlf9[9]      = {1,1,1,1,3,3,1,3,5};
__constant__ int c_finoff[3]    = {0,16,64};

// Precomputed tables (static device memory)
__device__ unsigned int   g_b1p[259];    // wcgb<<9 | yb<<4 | df
__device__ unsigned int   g_b2p[1104];   // gdst<<21 | cyb<<12 | fb<<4 | di
__device__ float          g_wcg[1225];   // cg * W[path]
__device__ unsigned short g_rmap[1216];  // src f4 -> padded smem f4

__device__ __forceinline__ void cp_async16(unsigned int smem_addr, const void* gptr) {
    asm volatile("cp.async.cg.shared.global [%0], [%1], 16;"
                 :: "r"(smem_addr), "l"(gptr));
}

__global__ void zero_kernel(float* out, int n) {
    int i = blockIdx.x * blockDim.x + threadIdx.x;
    if (i < n) out[i] = 0.f;
}

// Padded R layout per (lo,li) pair: 16 u-rows of (4*nlf+1) float4 each.
// Word stride 16nlf+4 == 20 (mod 32) -> conflict-free across u rows.
__device__ int map_r(int G4) {
    if (G4 < 256) { int r = G4 >> 6, l = G4 & 63; return r * 80 + (l >> 2) * 5 + (l & 3); }
    else if (G4 < 448) { int l = G4 - 256, u = l / 12; return 320 + u * 13 + (l - u * 12); }
    else if (G4 < 640) { int l = G4 - 448, u = l / 12; return 528 + u * 13 + (l - u * 12); }
    else if (G4 < 704) { int l = G4 - 640; return 736 + (l >> 2) * 5 + (l & 3); }
    else if (G4 < 896) { int l = G4 - 704, u = l / 12; return 816 + u * 13 + (l - u * 12); }
    else { int l = G4 - 896, u = l / 20; return 1024 + u * 21 + (l - u * 20); }
}

__global__ void build_tables(const float* __restrict__ cg, const float* __restrict__ W) {
    int t = blockIdx.x * blockDim.x + threadIdx.x;
    if (t < 259) {
        int p = 0;
        for (int q = 1; q < NPATH; ++q) if (t >= c_cyoff[q]) p = q;
        int j = t - c_cyoff[p], lf = c_lf[p], df = 2 * lf + 1;
        g_b1p[t] = ((unsigned)(c_cgoff[p] + j * df) << 9) | ((unsigned)(lf * lf) << 4) | (unsigned)df;
    }
    if (t < 1104) {
        int p = 0;
        for (int q = 1; q < NPATH; ++q) if (t >= c_b2off[q]) p = q;
        int j = t - c_b2off[p];
        int lo = c_lo[p], li = c_li[p];
        int doo = 2 * lo + 1, di = 2 * li + 1;
        int v = j / doo, o = j - v * doo;
        int pr = c_pair[p], nlf = c_nlf9[pr];
        int gdst = c_gw[pr] + o * (16 * nlf + 4) + v * nlf + c_k[p];
        g_b2p[t] = ((unsigned)gdst << 21) | ((unsigned)(c_cyoff[p] + o * di) << 12)
                 | ((unsigned)(c_finoff[li] + v * di) << 4) | (unsigned)di;
    }
    if (t < 1225) {
        int p = 0;
        for (int q = 1; q < NPATH; ++q) if (t >= c_cgoff[q]) p = q;
        g_wcg[t] = cg[t] * W[p];
    }
    if (t < 1216) g_rmap[t] = (unsigned short)map_r(t);
}

// acc += R_row . G_row over 4*NLF float4 from padded smem (conflict-free, broadcast-dedup)
template<int NLF>
__device__ __forceinline__ float pairdot_s(const float4* __restrict__ sR4,
                                           const float4* __restrict__ sG4,
                                           int rf4, int gf4, int u, int o) {
    const float4* r = sR4 + rf4 + u * (4 * NLF + 1);
    const float4* g = sG4 + gf4 + o * (4 * NLF + 1);
    float a0 = 0.f, a1 = 0.f, a2 = 0.f, a3 = 0.f;
    #pragma unroll
    for (int j = 0; j < 4 * NLF; ++j) {
        float4 A = r[j];
        float4 B = g[j];
        a0 = fmaf(A.x, B.x, a0);
        a1 = fmaf(A.y, B.y, a1);
        a2 = fmaf(A.z, B.z, a2);
        a3 = fmaf(A.w, B.w, a3);
    }
    return (a0 + a1) + (a2 + a3);
}

__global__ void __launch_bounds__(NT, 6)
tp_kernel(const float* __restrict__ feat, const float* __restrict__ rbf,
          const float* __restrict__ Y,    const int* __restrict__ aidx,
          const int* __restrict__ bidx,   float* __restrict__ out, int E)
{
    __shared__ float4 sR4[1360];   // padded R (21.8 KB)
    __shared__ float4 sG4[304];    // padded/interleaved W*G'' (4.9 KB)
    __shared__ float  sF[FEAT];
    __shared__ float  sY[YDIM];
    __shared__ float  sCY[259];

    const int e = blockIdx.x, tid = threadIdx.x;
    const int a = aidx[e];
    const int b = bidx[e];

    // ---- Phase A0: fire ALL R copies async (DRAM latency overlaps B1/B2) ----
    {
        const float4* r4 = reinterpret_cast<const float4*>(rbf + (size_t)e * EDGE_R);
        const unsigned int sR_base = (unsigned int)__cvta_generic_to_shared(sR4);
        #pragma unroll
        for (int i = 0; i < 5; ++i) {
            int t = tid + i * NT;
            if (t < 1216)
                cp_async16(sR_base + (unsigned)__ldg(&g_rmap[t]) * 16u, r4 + t);
        }
        asm volatile("cp.async.commit_group;");
    }

    // ---- Phase A1: F gather + Y (regular loads; B1 needs them first) ----
    if (tid < 36)
        reinterpret_cast<float4*>(sF)[tid] =
            reinterpret_cast<const float4*>(feat + (size_t)b * FEAT)[tid];
    if (tid >= 64 && tid < 64 + YDIM)
        sY[tid - 64] = Y[(size_t)e * YDIM + (tid - 64)];
    __syncthreads();

    // ---- Phase B1: CY[t] = sum_f wcg[wcgb+f] * Y[yb+f] ----
    if (tid < 259) {
        unsigned d = __ldg(&g_b1p[tid]);
        int df = d & 15, yb = (d >> 4) & 31, wb = d >> 9;
        float s = 0.f;
        for (int f = 0; f < df; ++f)
            s = fmaf(__ldg(&g_wcg[wb + f]), sY[yb + f], s);
        sCY[tid] = s;
    }
    __syncthreads();

    // ---- Phase B2: G''[gdst] = sum_i CY[cyb+i] * F[fb+i] ----
    float* sG = reinterpret_cast<float*>(sG4);
    for (int t = tid; t < 1104; t += NT) {
        unsigned d = __ldg(&g_b2p[t]);
        int di = d & 15, fb = (d >> 4) & 255, cyb = (d >> 12) & 511, gdst = d >> 21;
        float s = 0.f;
        for (int i = 0; i < di; ++i)
            s = fmaf(sCY[cyb + i], sF[fb + i], s);
        sG[gdst] = s;
    }

    // R copies must have landed (and G'' visible) before phase C
    asm volatile("cp.async.wait_group 0;");
    __syncthreads();

    // ---- Phase C: balanced split — two threads per lo=1/lo=2 output ----
    if (tid < 272) {
        float acc;
        int outi;
        if (tid < 16) {                          // lo=0 (48 FMA)
            const int u = tid;
            acc  = pairdot_s<1>(sR4, sG4,    0,   0, u, 0);
            acc += pairdot_s<1>(sR4, sG4,   80,   5, u, 0);
            acc += pairdot_s<1>(sR4, sG4,  160,  10, u, 0);
            outi = u;
        } else if (tid < 64) {                   // lo=1 h0 (64 FMA)
            const int s = tid - 16, u = s / 3, o = s - u * 3;
            acc  = pairdot_s<1>(sR4, sG4,  240,  15, u, o);
            acc += pairdot_s<3>(sR4, sG4,  320,  30, u, o);
            outi = 16 + u * 3 + o;
        } else if (tid < 112) {                  // lo=1 h1 (48 FMA)
            const int s = tid - 64, u = s / 3, o = s - u * 3;
            acc  = pairdot_s<3>(sR4, sG4,  528,  69, u, o);
            outi = 16 + u * 3 + o;
        } else if (tid < 192) {                  // lo=2 h0 (64 FMA)
            const int s = tid - 112, u = s / 5, o = s - u * 5;
            acc  = pairdot_s<1>(sR4, sG4,  736, 108, u, o);
            acc += pairdot_s<3>(sR4, sG4,  816, 133, u, o);
            outi = 64 + u * 5 + o;
        } else {                                 // lo=2 h1 (80 FMA)
            const int s = tid - 192, u = s / 5, o = s - u * 5;
            acc  = pairdot_s<5>(sR4, sG4, 1024, 198, u, o);
            outi = 64 + u * 5 + o;
        }
        atomicAdd(out + (size_t)a * FEAT + outi, acc);
    }
}

extern "C" void kernel_launch(void* const* d_in, const int* in_sizes, int n_in,
                              void* d_out, int out_size)
{
    const float* feat = (const float*)d_in[0];
    const float* rbf  = (const float*)d_in[1];
    const float* Y    = (const float*)d_in[2];
    const float* cg   = (const float*)d_in[3];
    const float* W    = (const float*)d_in[4];
    const int*   a    = (const int*)d_in[5];
    const int*   b    = (const int*)d_in[6];
    float* out = (float*)d_out;

    const int E = in_sizes[1] / EDGE_R;

    zero_kernel<<<(out_size + 255) / 256, 256>>>(out, out_size);
    build_tables<<<5, 256>>>(cg, W);
    tp_kernel<<<E, NT>>>(feat, rbf, Y, a, b, out, E);
}